// round 2
// baseline (speedup 1.0000x reference)
#include <cuda_runtime.h>

// CharAttention: B=512, W=128, c=24, C=32, H=2, D=16.
// Only the row at x_end_idx is needed -> compute a single causal attention row
// per (b,w) tile with folded weights:
//   M_h = W_q_h @ W_k_h^T / sqrt(D)   (score_h(k) = x_q M_h x_k^T)
//   P_h = W_v_h @ W_proj[h*D:(h+1)*D] (y = sum_h (sum_k att_hk x_k) P_h)
// out = x[idx] + y.

#define NTILES (512 * 128)
#define CBLK 24
#define EMB 32
#define WARPS 4
#define XSTRIDE 33  // pad: bank(33*r+i)%32 = (r+i)%32 -> conflict-free both ways

__device__ float g_M[2 * 32 * 32];  // [h][i][j]
__device__ float g_P[2 * 32 * 32];  // [h][i][j]

__global__ void precompute_kernel(const float* __restrict__ w_attn,
                                  const float* __restrict__ w_proj) {
    int t = blockIdx.x * blockDim.x + threadIdx.x;
    if (t >= 4096) return;
    int which = t >> 11;   // 0 = M, 1 = P
    int r = t & 2047;
    int h = r >> 10;
    int i = (r >> 5) & 31;
    int j = r & 31;
    float acc = 0.f;
    if (which == 0) {
        #pragma unroll
        for (int d = 0; d < 16; d++)
            acc += w_attn[i * 96 + h * 16 + d] * w_attn[j * 96 + 32 + h * 16 + d];
        g_M[r] = acc * 0.25f;  // 1/sqrt(16)
    } else {
        #pragma unroll
        for (int d = 0; d < 16; d++)
            acc += w_attn[i * 96 + 64 + h * 16 + d] * w_proj[(h * 16 + d) * 32 + j];
        g_P[r] = acc;
    }
}

__global__ void __launch_bounds__(WARPS * 32)
attn_kernel(const float* __restrict__ x, const int* __restrict__ endidx,
            float* __restrict__ out) {
    __shared__ float xs[WARPS][CBLK][XSTRIDE];
    __shared__ float4 qs4[WARPS][8];    // q vector (x row idx)
    __shared__ float4 us4[WARPS][16];   // packed (u0,u1) per dim
    __shared__ float4 ss4[WARPS][16];   // packed (s0,s1) per dim
    __shared__ float2 atts[WARPS][CBLK];

    const int w = threadIdx.x >> 5;
    const int lane = threadIdx.x & 31;

    // Per-lane column of each folded weight matrix lives in registers,
    // amortized across many tiles via grid-stride.
    float M0[32], M1[32], P0[32], P1[32];
    #pragma unroll
    for (int i = 0; i < 32; i++) {
        M0[i] = g_M[i * 32 + lane];
        M1[i] = g_M[1024 + i * 32 + lane];
        P0[i] = g_P[i * 32 + lane];
        P1[i] = g_P[1024 + i * 32 + lane];
    }

    const int warpGlobal = blockIdx.x * WARPS + w;
    const int warpStride = gridDim.x * WARPS;

    for (int bw = warpGlobal; bw < NTILES; bw += warpStride) {
        const int id = endidx[bw];
        const int nk = id + 1;
        const float* xt = x + (size_t)bw * (CBLK * EMB);
        const int totalF = nk * EMB;

        // ---- Stage rows 0..id of x through registers (MLP=6), then to smem.
        float4 v[6];
        #pragma unroll
        for (int k = 0; k < 6; k++) {
            int e = lane * 4 + k * 128;
            v[k] = make_float4(0.f, 0.f, 0.f, 0.f);
            if (e < totalF) v[k] = *reinterpret_cast<const float4*>(xt + e);
        }
        #pragma unroll
        for (int k = 0; k < 6; k++) {
            int e = lane * 4 + k * 128;
            if (e < totalF) {
                float* d = &xs[w][0][0] + (e >> 5) * XSTRIDE + (e & 31);
                d[0] = v[k].x; d[1] = v[k].y; d[2] = v[k].z; d[3] = v[k].w;
            }
        }
        __syncwarp();

        // ---- q = x[idx]  (conflict-free: bank (id+lane)%32)
        const float qv = xs[w][id][lane];
        reinterpret_cast<float*>(qs4[w])[lane] = qv;
        __syncwarp();

        // ---- u_h = q @ M_h   (lane = output dim j)
        float u0 = 0.f, u1 = 0.f;
        #pragma unroll
        for (int i4 = 0; i4 < 8; i4++) {
            const float4 q = qs4[w][i4];
            const int i = i4 * 4;
            u0 = fmaf(q.x, M0[i + 0], u0); u1 = fmaf(q.x, M1[i + 0], u1);
            u0 = fmaf(q.y, M0[i + 1], u0); u1 = fmaf(q.y, M1[i + 1], u1);
            u0 = fmaf(q.z, M0[i + 2], u0); u1 = fmaf(q.z, M1[i + 2], u1);
            u0 = fmaf(q.w, M0[i + 3], u0); u1 = fmaf(q.w, M1[i + 3], u1);
        }
        reinterpret_cast<float2*>(us4[w])[lane] = make_float2(u0, u1);
        __syncwarp();

        // ---- scores: lane = key r;  sc_h = u_h . x_r
        float sc0 = -1e30f, sc1 = -1e30f;
        if (lane < nk) {
            float a = 0.f, b = 0.f;
            const float* xr = &xs[w][lane][0];  // bank (lane+i)%32: conflict-free
            #pragma unroll
            for (int i2 = 0; i2 < 16; i2++) {
                const float4 uu = us4[w][i2];  // broadcast
                const float x0 = xr[2 * i2];
                const float x1 = xr[2 * i2 + 1];
                a = fmaf(uu.x, x0, a); b = fmaf(uu.y, x0, b);
                a = fmaf(uu.z, x1, a); b = fmaf(uu.w, x1, b);
            }
            sc0 = a; sc1 = b;
        }

        // ---- softmax over keys (unnormalized; divide at the end)
        float m0 = sc0, m1 = sc1;
        #pragma unroll
        for (int o = 16; o > 0; o >>= 1) {
            m0 = fmaxf(m0, __shfl_xor_sync(0xffffffffu, m0, o));
            m1 = fmaxf(m1, __shfl_xor_sync(0xffffffffu, m1, o));
        }
        float e0 = 0.f, e1 = 0.f;
        if (lane < nk) { e0 = __expf(sc0 - m0); e1 = __expf(sc1 - m1); }
        float sum0 = e0, sum1 = e1;
        #pragma unroll
        for (int o = 16; o > 0; o >>= 1) {
            sum0 += __shfl_xor_sync(0xffffffffu, sum0, o);
            sum1 += __shfl_xor_sync(0xffffffffu, sum1, o);
        }
        if (lane < CBLK) atts[w][lane] = make_float2(e0, e1);
        __syncwarp();

        // ---- s_h = sum_r att_hr * x_r   (lane = dim i)
        float a0 = 0.f, a1 = 0.f;
        for (int r = 0; r < nk; r++) {
            const float2 ar = atts[w][r];       // broadcast
            const float xv = xs[w][r][lane];    // conflict-free
            a0 = fmaf(ar.x, xv, a0);
            a1 = fmaf(ar.y, xv, a1);
        }
        a0 = __fdividef(a0, sum0);
        a1 = __fdividef(a1, sum1);
        reinterpret_cast<float2*>(ss4[w])[lane] = make_float2(a0, a1);
        __syncwarp();

        // ---- y = sum_h s_h @ P_h, residual, store
        float y = 0.f;
        #pragma unroll
        for (int i2 = 0; i2 < 16; i2++) {
            const float4 sv = ss4[w][i2];
            y = fmaf(sv.x, P0[2 * i2], y);
            y = fmaf(sv.y, P1[2 * i2], y);
            y = fmaf(sv.z, P0[2 * i2 + 1], y);
            y = fmaf(sv.w, P1[2 * i2 + 1], y);
        }
        out[bw * EMB + lane] = qv + y;
        __syncwarp();  // protect smem reuse on next grid-stride iteration
    }
}

extern "C" void kernel_launch(void* const* d_in, const int* in_sizes, int n_in,
                              void* d_out, int out_size) {
    const float* x      = (const float*)d_in[0];
    const int*   endidx = (const int*)d_in[1];
    const float* w_attn = (const float*)d_in[2];
    const float* w_proj = (const float*)d_in[3];
    float* out = (float*)d_out;

    precompute_kernel<<<16, 256>>>(w_attn, w_proj);
    attn_kernel<<<444, WARPS * 32>>>(x, endidx, out);
}

// round 3
// speedup vs baseline: 1.4615x; 1.4615x over previous
#include <cuda_runtime.h>

// CharAttention: B=512, W=128, c=24, C=32, H=2, D=16.
// Only the row at x_end_idx is needed -> one causal attention row per (b,w)
// tile with folded weights:
//   M_h = W_q_h @ W_k_h^T / sqrt(D)   (score_h(k) = x_q M_h x_k^T)
//   P_h = W_v_h @ W_proj[h*D:(h+1)*D] (y = sum_h (sum_k att_hk x_k) P_h)
// out = x[idx] + y.
// Round 2: two warps per tile (one per head) -> 64 weight regs/thread instead
// of 128, ~2.5x occupancy; float4 LDS; named-barrier pair sync; idx prefetch.

#define NTILES (512 * 128)
#define CBLK 24
#define EMB 32
#define XSTRIDE 36      // pad (mult of 4, %32==4): conflict-free for float4-row and scalar-column
#define PAIRS_PER_BLK 4
#define THREADS (PAIRS_PER_BLK * 64)
#define GRID 296        // 2 blocks/SM * 148 SMs

__device__ float g_M[2 * 32 * 32];  // [h][i][j]
__device__ float g_P[2 * 32 * 32];  // [h][i][j]

__global__ void precompute_kernel(const float* __restrict__ w_attn,
                                  const float* __restrict__ w_proj) {
    int t = blockIdx.x * blockDim.x + threadIdx.x;
    if (t >= 4096) return;
    int which = t >> 11;   // 0 = M, 1 = P
    int r = t & 2047;
    int h = r >> 10;
    int i = (r >> 5) & 31;
    int j = r & 31;
    float acc = 0.f;
    if (which == 0) {
        #pragma unroll
        for (int d = 0; d < 16; d++)
            acc += w_attn[i * 96 + h * 16 + d] * w_attn[j * 96 + 32 + h * 16 + d];
        g_M[r] = acc * 0.25f;  // 1/sqrt(16)
    } else {
        #pragma unroll
        for (int d = 0; d < 16; d++)
            acc += w_attn[i * 96 + 64 + h * 16 + d] * w_proj[(h * 16 + d) * 32 + j];
        g_P[r] = acc;
    }
}

__global__ void __launch_bounds__(THREADS, 2)
attn_kernel(const float* __restrict__ x, const int* __restrict__ endidx,
            float* __restrict__ out) {
    __shared__ __align__(16) float xs[PAIRS_PER_BLK][CBLK][XSTRIDE];
    __shared__ float4 qs4[2 * PAIRS_PER_BLK][8];  // per-warp private q copy
    __shared__ float4 us4[2 * PAIRS_PER_BLK][8];  // per-warp u_h (32 floats)
    __shared__ float4 ss4[2 * PAIRS_PER_BLK][8];  // per-warp s_h (32 floats)
    __shared__ float  atts[2 * PAIRS_PER_BLK][CBLK];
    __shared__ float  y1s[PAIRS_PER_BLK][32];

    const int w    = threadIdx.x >> 5;   // warp in block
    const int lane = threadIdx.x & 31;
    const int p    = w >> 1;             // pair in block
    const int h    = w & 1;              // head handled by this warp
    const int pt   = (h << 5) | lane;    // thread index within pair (0..63)
    const int barId = p + 1;             // named barrier per pair

    // This warp's head's folded-weight columns (lane = output dim j).
    float Mc[32], Pc[32];
    {
        const float* Mb = g_M + h * 1024 + lane;
        const float* Pb = g_P + h * 1024 + lane;
        #pragma unroll
        for (int i = 0; i < 32; i++) { Mc[i] = Mb[i * 32]; Pc[i] = Pb[i * 32]; }
    }

    const int pairGlobal = blockIdx.x * PAIRS_PER_BLK + p;
    const int pairStride = GRID * PAIRS_PER_BLK;

    int bw = pairGlobal;
    if (bw >= NTILES) return;
    int id = endidx[bw];

    while (bw < NTILES) {
        const int bwn = bw + pairStride;
        const int id_next = (bwn < NTILES) ? __ldg(endidx + bwn) : 0;

        const int nk = id + 1;
        const int totalF = nk * EMB;
        const float* xt = x + (size_t)bw * (CBLK * EMB);

        // ---- Stage rows 0..id of x (64 threads, 3 predicated float4 each).
        float4 v[3];
        #pragma unroll
        for (int k = 0; k < 3; k++) {
            int e = pt * 4 + k * 256;
            if (e < totalF) v[k] = *reinterpret_cast<const float4*>(xt + e);
        }
        #pragma unroll
        for (int k = 0; k < 3; k++) {
            int e = pt * 4 + k * 256;
            if (e < totalF)
                *reinterpret_cast<float4*>(&xs[p][e >> 5][e & 31]) = v[k];
        }
        asm volatile("bar.sync %0, 64;" :: "r"(barId) : "memory");

        // ---- q = x[idx] (conflict-free column read); private copy per warp.
        const float qv = xs[p][id][lane];
        reinterpret_cast<float*>(qs4[w])[lane] = qv;
        __syncwarp();

        // ---- u = q @ M_h   (lane = output dim j)
        float u = 0.f;
        #pragma unroll
        for (int i4 = 0; i4 < 8; i4++) {
            const float4 q = qs4[w][i4];
            const int i = i4 * 4;
            u = fmaf(q.x, Mc[i + 0], u);
            u = fmaf(q.y, Mc[i + 1], u);
            u = fmaf(q.z, Mc[i + 2], u);
            u = fmaf(q.w, Mc[i + 3], u);
        }
        reinterpret_cast<float*>(us4[w])[lane] = u;
        __syncwarp();

        // ---- scores: lane = key r; sc = u . x_r  (float4 row reads)
        float sc = -1e30f;
        if (lane < nk) {
            const float4* xr = reinterpret_cast<const float4*>(&xs[p][lane][0]);
            float a = 0.f;
            #pragma unroll
            for (int i4 = 0; i4 < 8; i4++) {
                const float4 uu = us4[w][i4];   // broadcast
                const float4 xv = xr[i4];
                a = fmaf(uu.x, xv.x, a);
                a = fmaf(uu.y, xv.y, a);
                a = fmaf(uu.z, xv.z, a);
                a = fmaf(uu.w, xv.w, a);
            }
            sc = a;
        }

        // ---- softmax over keys (unnormalized; divide at the end)
        float m = sc;
        #pragma unroll
        for (int o = 16; o > 0; o >>= 1)
            m = fmaxf(m, __shfl_xor_sync(0xffffffffu, m, o));
        float e = (lane < nk) ? __expf(sc - m) : 0.f;
        float sum = e;
        #pragma unroll
        for (int o = 16; o > 0; o >>= 1)
            sum += __shfl_xor_sync(0xffffffffu, sum, o);
        if (lane < CBLK) atts[w][lane] = e;
        __syncwarp();

        // ---- s = sum_r att_r * x_r   (lane = dim i)
        float a0 = 0.f;
        for (int r = 0; r < nk; r++)
            a0 = fmaf(atts[w][r], xs[p][r][lane], a0);
        a0 = __fdividef(a0, sum);
        reinterpret_cast<float*>(ss4[w])[lane] = a0;
        __syncwarp();

        // ---- y_h = s @ P_h   (lane = output dim j)
        float y = 0.f;
        #pragma unroll
        for (int i4 = 0; i4 < 8; i4++) {
            const float4 sv = ss4[w][i4];
            const int i = i4 * 4;
            y = fmaf(sv.x, Pc[i + 0], y);
            y = fmaf(sv.y, Pc[i + 1], y);
            y = fmaf(sv.z, Pc[i + 2], y);
            y = fmaf(sv.w, Pc[i + 3], y);
        }

        // ---- combine heads, residual, store
        if (h == 1) y1s[p][lane] = y;
        asm volatile("bar.sync %0, 64;" :: "r"(barId) : "memory");
        if (h == 0) out[bw * EMB + lane] = qv + y + y1s[p][lane];

        bw = bwn;
        id = id_next;
    }
}

extern "C" void kernel_launch(void* const* d_in, const int* in_sizes, int n_in,
                              void* d_out, int out_size) {
    const float* x      = (const float*)d_in[0];
    const int*   endidx = (const int*)d_in[1];
    const float* w_attn = (const float*)d_in[2];
    const float* w_proj = (const float*)d_in[3];
    float* out = (float*)d_out;

    precompute_kernel<<<16, 256>>>(w_attn, w_proj);
    attn_kernel<<<GRID, THREADS>>>(x, endidx, out);
}

// round 5
// speedup vs baseline: 1.6927x; 1.1582x over previous
#include <cuda_runtime.h>

// CharAttention: B=512, W=128, c=24, C=32, H=2, D=16.
// Only the row at x_end_idx is needed -> one causal attention row per (b,w)
// tile with folded weights:
//   M_h = W_q_h @ W_k_h^T / sqrt(D)   (score_h(k) = x_q M_h x_k^T)
//   P_h = W_v_h @ W_proj[h*D:(h+1)*D] (y = sum_h (sum_k att_hk x_k) P_h)
// out = x[idx] + y.
// R2: warp-pair per tile (one head each), 64 weight regs/thread.
// R3: software pipeline — double-buffered x tile, LDG for tile n+1 issued
//     behind tile n's barrier, idx prefetched 2 tiles ahead, ONE bar per tile
//     (head-combine folded into the next staging barrier).

#define NTILES (512 * 128)
#define CBLK 24
#define EMB 32
#define XSTRIDE 36      // pad (mult of 4, %32==4): conflict-free float4-row AND scalar-column
#define PAIRS_PER_BLK 4
#define THREADS (PAIRS_PER_BLK * 64)
#define GRID 296        // 2 blocks/SM * 148 SMs -> fully persistent
#define PAIRSTRIDE (GRID * PAIRS_PER_BLK)

__device__ float g_M[2 * 32 * 32];  // [h][i][j]
__device__ float g_P[2 * 32 * 32];  // [h][i][j]

__global__ void precompute_kernel(const float* __restrict__ w_attn,
                                  const float* __restrict__ w_proj) {
    int t = blockIdx.x * blockDim.x + threadIdx.x;
    if (t >= 4096) return;
    int which = t >> 11;   // 0 = M, 1 = P
    int r = t & 2047;
    int h = r >> 10;
    int i = (r >> 5) & 31;
    int j = r & 31;
    float acc = 0.f;
    if (which == 0) {
        #pragma unroll
        for (int d = 0; d < 16; d++)
            acc += w_attn[i * 96 + h * 16 + d] * w_attn[j * 96 + 32 + h * 16 + d];
        g_M[r] = acc * 0.25f;  // 1/sqrt(16)
    } else {
        #pragma unroll
        for (int d = 0; d < 16; d++)
            acc += w_attn[i * 96 + 64 + h * 16 + d] * w_proj[(h * 16 + d) * 32 + j];
        g_P[r] = acc;
    }
}

__global__ void __launch_bounds__(THREADS, 2)
attn_kernel(const float* __restrict__ x, const int* __restrict__ endidx,
            float* __restrict__ out) {
    __shared__ __align__(16) float xs[2][PAIRS_PER_BLK][CBLK][XSTRIDE];
    __shared__ float4 qs4[2 * PAIRS_PER_BLK][8];   // per-warp private q copy
    __shared__ float4 us4[2 * PAIRS_PER_BLK][8];   // per-warp u_h
    __shared__ float4 ss4[2 * PAIRS_PER_BLK][8];   // per-warp s_h
    __shared__ float  atts[2 * PAIRS_PER_BLK][CBLK];
    __shared__ float  y1s[PAIRS_PER_BLK][2][32];   // head-1 output, parity-buffered

    const int w    = threadIdx.x >> 5;
    const int lane = threadIdx.x & 31;
    const int p    = w >> 1;             // pair in block
    const int h    = w & 1;              // head handled by this warp
    const int pt   = (h << 5) | lane;    // thread within pair (0..63)
    const int barId = p + 1;

    // This warp's head's folded-weight columns (lane = output dim j).
    float Mc[32], Pc[32];
    {
        const float* Mb = g_M + h * 1024 + lane;
        const float* Pb = g_P + h * 1024 + lane;
        #pragma unroll
        for (int i = 0; i < 32; i++) { Mc[i] = Mb[i * 32]; Pc[i] = Pb[i * 32]; }
    }

    int bw = blockIdx.x * PAIRS_PER_BLK + p;

    // ---- Pipeline prologue: idx two tiles ahead, x one tile ahead.
    int id  = __ldg(endidx + bw);                                 // tile n
    int bw1 = bw + PAIRSTRIDE;
    int id1 = (bw1 < NTILES) ? __ldg(endidx + bw1) : 0;           // tile n+1

    float4 v[3];
    {
        const float* xt = x + (size_t)bw * (CBLK * EMB);
        const int totalF = (id + 1) * EMB;
        #pragma unroll
        for (int k = 0; k < 3; k++) {
            int e = pt * 4 + k * 256;
            if (e < totalF) v[k] = *reinterpret_cast<const float4*>(xt + e);
        }
    }

    int buf = 0;
    int   prev_bw = -1;
    float prev_qv = 0.f, prev_y = 0.f;

    while (bw < NTILES) {
        const int nk = id + 1;

        // ---- Commit staged tile n to smem.
        {
            const int totalF = nk * EMB;
            #pragma unroll
            for (int k = 0; k < 3; k++) {
                int e = pt * 4 + k * 256;
                if (e < totalF)
                    *reinterpret_cast<float4*>(&xs[buf][p][e >> 5][e & 31]) = v[k];
            }
        }
        asm volatile("bar.sync %0, 64;" :: "r"(barId) : "memory");

        // ---- Store tile n-1 output (warp0); y1s written by warp1 pre-bar.
        if (h == 0 && prev_bw >= 0)
            out[prev_bw * EMB + lane] = prev_qv + prev_y + y1s[p][buf ^ 1][lane];

        // ---- Prefetch: idx for tile n+2, x for tile n+1 (latency hidden
        //      behind this tile's compute).
        const int bw2 = bw1 + PAIRSTRIDE;
        const int id2 = (bw2 < NTILES) ? __ldg(endidx + bw2) : 0;
        if (bw1 < NTILES) {
            const float* xt = x + (size_t)bw1 * (CBLK * EMB);
            const int totalF = (id1 + 1) * EMB;
            #pragma unroll
            for (int k = 0; k < 3; k++) {
                int e = pt * 4 + k * 256;
                if (e < totalF) v[k] = *reinterpret_cast<const float4*>(xt + e);
            }
        }

        // ---- q = x[idx] (conflict-free column read); private warp copy.
        const float qv = xs[buf][p][id][lane];
        reinterpret_cast<float*>(qs4[w])[lane] = qv;
        __syncwarp();

        // ---- u = q @ M_h   (lane = output dim j)
        float u = 0.f;
        #pragma unroll
        for (int i4 = 0; i4 < 8; i4++) {
            const float4 q = qs4[w][i4];
            const int i = i4 * 4;
            u = fmaf(q.x, Mc[i + 0], u);
            u = fmaf(q.y, Mc[i + 1], u);
            u = fmaf(q.z, Mc[i + 2], u);
            u = fmaf(q.w, Mc[i + 3], u);
        }
        reinterpret_cast<float*>(us4[w])[lane] = u;
        __syncwarp();

        // ---- scores: lane = key r; sc = u . x_r (float4 row reads)
        float sc = -1e30f;
        if (lane < nk) {
            const float4* xr = reinterpret_cast<const float4*>(&xs[buf][p][lane][0]);
            float a = 0.f;
            #pragma unroll
            for (int i4 = 0; i4 < 8; i4++) {
                const float4 uu = us4[w][i4];   // broadcast
                const float4 xv = xr[i4];
                a = fmaf(uu.x, xv.x, a);
                a = fmaf(uu.y, xv.y, a);
                a = fmaf(uu.z, xv.z, a);
                a = fmaf(uu.w, xv.w, a);
            }
            sc = a;
        }

        // ---- softmax over keys (unnormalized; divide at the end)
        float m = sc;
        #pragma unroll
        for (int o = 16; o > 0; o >>= 1)
            m = fmaxf(m, __shfl_xor_sync(0xffffffffu, m, o));
        float e = (lane < nk) ? __expf(sc - m) : 0.f;
        float sum = e;
        #pragma unroll
        for (int o = 16; o > 0; o >>= 1)
            sum += __shfl_xor_sync(0xffffffffu, sum, o);
        if (lane < CBLK) atts[w][lane] = e;
        __syncwarp();

        // ---- s = sum_r att_r * x_r   (lane = dim i)
        float a0 = 0.f;
        for (int r = 0; r < nk; r++)
            a0 = fmaf(atts[w][r], xs[buf][p][r][lane], a0);
        a0 = __fdividef(a0, sum);
        reinterpret_cast<float*>(ss4[w])[lane] = a0;
        __syncwarp();

        // ---- y_h = s @ P_h   (lane = output dim j)
        float y = 0.f;
        #pragma unroll
        for (int i4 = 0; i4 < 8; i4++) {
            const float4 sv = ss4[w][i4];
            const int i = i4 * 4;
            y = fmaf(sv.x, Pc[i + 0], y);
            y = fmaf(sv.y, Pc[i + 1], y);
            y = fmaf(sv.z, Pc[i + 2], y);
            y = fmaf(sv.w, Pc[i + 3], y);
        }

        // ---- defer combine: warp1 publishes, warp0 stores after next bar.
        if (h == 1) {
            y1s[p][buf][lane] = y;
        } else {
            prev_qv = qv; prev_y = y; prev_bw = bw;
        }

        bw = bw1; id = id1;
        bw1 = bw2; id1 = id2;
        buf ^= 1;
    }

    // ---- Epilogue: flush last tile's output.
    asm volatile("bar.sync %0, 64;" :: "r"(barId) : "memory");
    if (h == 0 && prev_bw >= 0)
        out[prev_bw * EMB + lane] = prev_qv + prev_y + y1s[p][buf ^ 1][lane];
}

extern "C" void kernel_launch(void* const* d_in, const int* in_sizes, int n_in,
                              void* d_out, int out_size) {
    const float* x      = (const float*)d_in[0];
    const int*   endidx = (const int*)d_in[1];
    const float* w_attn = (const float*)d_in[2];
    const float* w_proj = (const float*)d_in[3];
    float* out = (float*)d_out;

    precompute_kernel<<<16, 256>>>(w_attn, w_proj);
    attn_kernel<<<GRID, THREADS>>>(x, endidx, out);
}